// round 9
// baseline (speedup 1.0000x reference)
#include <cuda_runtime.h>
#include <cstdint>

// Problem constants (fixed by the dataset)
#define NN 50000
#define EE 800000
#define HH 64
#define GG 128
#define CC 16
#define CAP 64   // per-node bucket capacity (mean deg = 16; P(deg>63) ~ e^-39)
#define GR 128   // gemm rows per block

// ---------------- device scratch (static, no allocations) ----------------
__device__ int   g_deg[NN];                    // in-degree / bucket fill
__device__ float g_dinv[NN];
__device__ int   g_srcs[(size_t)NN * CAP];     // bucketed CSR
__device__ float g_feat[(size_t)NN * HH];      // g = (X@W) * dinv
__device__ float g_h1[(size_t)NN * HH];        // layer-1 output (post relu)
__device__ int   g_goff[GG + 1];
__device__ int   g_is64;

// ---------------- index dtype handling ----------------
__device__ __forceinline__ int idx_at(const void* p, int is64, long long i) {
    if (is64) return (int)__ldg(((const long long*)p) + i);
    return __ldg(((const int*)p) + i);
}

// Zero counters + detect index dtype (int64 vs int32).
__global__ void zero_kernel(const void* __restrict__ ei) {
    int i = blockIdx.x * blockDim.x + threadIdx.x;
    int stride = gridDim.x * blockDim.x;
    for (; i < NN; i += stride) g_deg[i] = 0;
    if (blockIdx.x == 0 && threadIdx.x == 0) {
        const unsigned long long* p = (const unsigned long long*)ei;
        int ok = 1;
        for (int t = 0; t < 16; t++)
            if (p[t] >= (unsigned long long)NN) ok = 0;
        g_is64 = ok;
    }
}

// Single-pass bucketed CSR build, unrolled x4 for atomic-latency overlap.
__global__ __launch_bounds__(256) void scatter_kernel(const void* __restrict__ ei) {
    const int U = 4;
    int is64 = g_is64;
    int stride = gridDim.x * blockDim.x;
    int base = blockIdx.x * blockDim.x + threadIdx.x;

    int s[U], d[U], p[U];
    bool ok[U];
#pragma unroll
    for (int u = 0; u < U; u++) {
        int e = base + u * stride;
        ok[u] = (e < EE);
        if (ok[u]) {
            s[u] = idx_at(ei, is64, e);
            d[u] = idx_at(ei, is64, (long long)EE + e);
        }
    }
#pragma unroll
    for (int u = 0; u < U; u++)
        if (ok[u]) p[u] = atomicAdd(&g_deg[d[u]], 1);
#pragma unroll
    for (int u = 0; u < U; u++)
        if (ok[u] && p[u] < CAP) g_srcs[(size_t)d[u] * CAP + p[u]] = s[u];
}

// dinv from final degrees + graph offsets from sorted-batch boundaries.
__global__ void meta_kernel(const void* __restrict__ bat) {
    int is64 = g_is64;
    int i = blockIdx.x * blockDim.x + threadIdx.x;
    int stride = gridDim.x * blockDim.x;
    for (int n = i; n < NN; n += stride) {
        g_dinv[n] = rsqrtf((float)(g_deg[n] + 1));
        int b = idx_at(bat, is64, n);
        int bp = (n == 0) ? -1 : idx_at(bat, is64, n - 1);
        for (int g = bp + 1; g <= b; g++) g_goff[g] = n;
        if (n == NN - 1)
            for (int g = b + 1; g <= GG; g++) g_goff[g] = NN;
    }
}

// packed fp32x2 fma: d = a*b + c (per 32-bit half)
__device__ __forceinline__ void ffma2(unsigned long long& d,
                                      unsigned long long a,
                                      unsigned long long b) {
    asm("fma.rn.f32x2 %0, %1, %2, %0;" : "+l"(d) : "l"(a), "l"(b));
}

// out[row,:] = (X[row,:] @ W) * dinv[row].
// 128-row tiles, 128 threads, thread tile = 8 rows x 8 cols, FFMA2 kernel:
// 64-bit regs pack 2 ROWS (from transposed Xs); W duplicated in smem so
// each 64-bit w operand is (w_j, w_j).
__global__ __launch_bounds__(128) void gemm64(const float* __restrict__ X,
                                              const float* __restrict__ W,
                                              float* __restrict__ out,
                                              int n) {
    __shared__ float Xs[64][GR + 4];    // [k][row] transposed
    __shared__ float Wd[64][132];       // [k][2*col] duplicated pairs
    const int tid = threadIdx.x;
    const int brow = blockIdx.x * GR;

    // load W duplicated: Wd[r][2c+0..1] = (W[r][c], W[r][c])
    for (int t = tid; t < 64 * 16; t += 128) {
        int r = t >> 4, c = (t & 15) << 2;
        float4 w = *(const float4*)(W + r * 64 + c);
        float4 d0 = make_float4(w.x, w.x, w.y, w.y);
        float4 d1 = make_float4(w.z, w.z, w.w, w.w);
        *(float4*)&Wd[r][2 * c] = d0;
        *(float4*)&Wd[r][2 * c + 4] = d1;
    }
    // load X tile transposed
    for (int t = tid; t < GR * 16; t += 128) {
        int r = t >> 4, c = (t & 15) << 2;
        int grow = brow + r;
        float4 v = make_float4(0.f, 0.f, 0.f, 0.f);
        if (grow < n) v = *(const float4*)(X + (size_t)grow * 64 + c);
        Xs[c][r] = v.x; Xs[c + 1][r] = v.y; Xs[c + 2][r] = v.z; Xs[c + 3][r] = v.w;
    }
    __syncthreads();

    const int r0 = (tid >> 3) << 3;   // 8 consecutive rows (4 row-pairs)
    const int j0 = (tid & 7) << 3;    // 8 consecutive cols

    unsigned long long acc[4][8];     // [row-pair][col], each = 2 rows packed
#pragma unroll
    for (int i = 0; i < 4; i++)
#pragma unroll
        for (int j = 0; j < 8; j++) acc[i][j] = 0ull;

#pragma unroll
    for (int k = 0; k < 64; k++) {
        // 4 row-pairs: rows r0..r0+7, packed 2-per-64bit (contiguous in Xs)
        ulonglong2 xa = *(const ulonglong2*)&Xs[k][r0];
        ulonglong2 xb = *(const ulonglong2*)&Xs[k][r0 + 4];
        unsigned long long xp[4] = {xa.x, xa.y, xb.x, xb.y};
        // 8 duplicated w pairs: Wd[k][2*j0 .. 2*j0+15]
        ulonglong2 wa = *(const ulonglong2*)&Wd[k][2 * j0];
        ulonglong2 wb = *(const ulonglong2*)&Wd[k][2 * j0 + 4];
        ulonglong2 wc = *(const ulonglong2*)&Wd[k][2 * j0 + 8];
        ulonglong2 wd = *(const ulonglong2*)&Wd[k][2 * j0 + 12];
        unsigned long long wp[8] = {wa.x, wa.y, wb.x, wb.y, wc.x, wc.y, wd.x, wd.y};
#pragma unroll
        for (int i = 0; i < 4; i++)
#pragma unroll
            for (int j = 0; j < 8; j++)
                ffma2(acc[i][j], xp[i], wp[j]);
    }

    // epilogue: unpack row pairs, scale by dinv, store
#pragma unroll
    for (int i = 0; i < 4; i++) {
        int rowlo = brow + r0 + 2 * i;
        int rowhi = rowlo + 1;
        float lo[8], hi[8];
#pragma unroll
        for (int j = 0; j < 8; j++) {
            unsigned int l, h;
            asm("mov.b64 {%0, %1}, %2;" : "=r"(l), "=r"(h) : "l"(acc[i][j]));
            lo[j] = __uint_as_float(l);
            hi[j] = __uint_as_float(h);
        }
        if (rowlo < n) {
            float dv = g_dinv[rowlo];
            float4 o0 = make_float4(lo[0] * dv, lo[1] * dv, lo[2] * dv, lo[3] * dv);
            float4 o1 = make_float4(lo[4] * dv, lo[5] * dv, lo[6] * dv, lo[7] * dv);
            *(float4*)(out + (size_t)rowlo * 64 + j0) = o0;
            *(float4*)(out + (size_t)rowlo * 64 + j0 + 4) = o1;
        }
        if (rowhi < n) {
            float dv = g_dinv[rowhi];
            float4 o0 = make_float4(hi[0] * dv, hi[1] * dv, hi[2] * dv, hi[3] * dv);
            float4 o1 = make_float4(hi[4] * dv, hi[5] * dv, hi[6] * dv, hi[7] * dv);
            *(float4*)(out + (size_t)rowhi * 64 + j0) = o0;
            *(float4*)(out + (size_t)rowhi * 64 + j0 + 4) = o1;
        }
    }
}

// Pull-style aggregation: one warp per node, 2 edges per step (half-warps),
// inner loop unrolled x2 -> 4 independent gathers in flight per warp.
template <bool RELU>
__global__ __launch_bounds__(256) void agg_kernel(const float* __restrict__ gb,
                                                  const float* __restrict__ bias,
                                                  float* __restrict__ out) {
    int warp = (blockIdx.x * blockDim.x + threadIdx.x) >> 5;
    if (warp >= NN) return;
    int lane = threadIdx.x & 31;
    int sub = lane >> 4;          // which of 2 edges per step
    int fc = (lane & 15) << 2;    // feature offset (float4)
    int beg = warp * CAP;
    int end = beg + min(g_deg[warp], CAP);

    float4 accA, accB = make_float4(0.f, 0.f, 0.f, 0.f);
    if (sub == 0) {               // self-loop term loaded once by half-warp 0
        accA = *(const float4*)(gb + (size_t)warp * 64 + fc);
    } else {
        accA = make_float4(0.f, 0.f, 0.f, 0.f);
    }

    int e = beg + sub;
    for (; e + 2 < end; e += 4) {
        int s0 = __ldg(&g_srcs[e]);
        int s1 = __ldg(&g_srcs[e + 2]);
        float4 v0 = __ldg((const float4*)(gb + (size_t)s0 * 64 + fc));
        float4 v1 = __ldg((const float4*)(gb + (size_t)s1 * 64 + fc));
        accA.x += v0.x; accA.y += v0.y; accA.z += v0.z; accA.w += v0.w;
        accB.x += v1.x; accB.y += v1.y; accB.z += v1.z; accB.w += v1.w;
    }
    if (e < end) {
        int s0 = __ldg(&g_srcs[e]);
        float4 v0 = __ldg((const float4*)(gb + (size_t)s0 * 64 + fc));
        accA.x += v0.x; accA.y += v0.y; accA.z += v0.z; accA.w += v0.w;
    }
    accA.x += accB.x; accA.y += accB.y; accA.z += accB.z; accA.w += accB.w;

    // combine the two half-warps
    accA.x += __shfl_xor_sync(0xffffffffu, accA.x, 16);
    accA.y += __shfl_xor_sync(0xffffffffu, accA.y, 16);
    accA.z += __shfl_xor_sync(0xffffffffu, accA.z, 16);
    accA.w += __shfl_xor_sync(0xffffffffu, accA.w, 16);

    if (sub == 0) {
        float dv = g_dinv[warp];
        float4 b = __ldg((const float4*)(bias + fc));
        float4 o;
        o.x = fmaf(accA.x, dv, b.x);
        o.y = fmaf(accA.y, dv, b.y);
        o.z = fmaf(accA.z, dv, b.z);
        o.w = fmaf(accA.w, dv, b.w);
        if (RELU) {
            o.x = fmaxf(o.x, 0.f); o.y = fmaxf(o.y, 0.f);
            o.z = fmaxf(o.z, 0.f); o.w = fmaxf(o.w, 0.f);
        }
        *(float4*)(out + (size_t)warp * 64 + fc) = o;
    }
}

// Fused mean pool + classifier: one block per graph, 64 threads.
__global__ __launch_bounds__(64) void poolcls_kernel(
        const float* __restrict__ h, float* __restrict__ reps,
        const float* __restrict__ Wc1, const float* __restrict__ bc1,
        const float* __restrict__ Wc2, const float* __restrict__ bc2,
        float* __restrict__ logits) {
    __shared__ float rep[64];
    __shared__ float tbuf[64];
    int g = blockIdx.x, tid = threadIdx.x;
    int beg = g_goff[g], end = g_goff[g + 1];
    float s = 0.f;
    for (int i = beg; i < end; i++) s += __ldg(h + (size_t)i * 64 + tid);
    float c = (float)max(end - beg, 1);
    float r = s / c;
    reps[g * 64 + tid] = r;
    rep[tid] = r;
    __syncthreads();
    float acc = bc1[tid];
#pragma unroll
    for (int k = 0; k < 64; k++) acc = fmaf(rep[k], __ldg(Wc1 + k * 64 + tid), acc);
    tbuf[tid] = fmaxf(acc, 0.f);
    __syncthreads();
    if (tid < CC) {
        float a = bc2[tid];
#pragma unroll
        for (int k = 0; k < 64; k++) a = fmaf(tbuf[k], __ldg(Wc2 + k * CC + tid), a);
        logits[g * CC + tid] = a;
    }
}

extern "C" void kernel_launch(void* const* d_in, const int* in_sizes, int n_in,
                              void* d_out, int out_size) {
    const float* x   = (const float*)d_in[0];
    const void*  ei  = d_in[1];
    const void*  bat = d_in[2];
    const float* W1  = (const float*)d_in[3];
    const float* b1  = (const float*)d_in[4];
    const float* W2  = (const float*)d_in[5];
    const float* b2  = (const float*)d_in[6];
    const float* Wc1 = (const float*)d_in[7];
    const float* bc1 = (const float*)d_in[8];
    const float* Wc2 = (const float*)d_in[9];
    const float* bc2 = (const float*)d_in[10];

    float* out_h   = (float*)d_out;                       // [NN, 64]
    float* out_rep = out_h + (size_t)NN * HH;             // [128, 64]
    float* out_log = out_rep + (size_t)GG * HH;           // [128, 16]

    void* pv;
    cudaGetSymbolAddress(&pv, g_feat);
    float* p_feat = (float*)pv;
    cudaGetSymbolAddress(&pv, g_h1);
    float* p_h1 = (float*)pv;

    const int gemm_blocks = (NN + GR - 1) / GR;
    const int agg_blocks = (NN * 32 + 255) / 256;
    const int scat_blocks = (EE + 256 * 4 - 1) / (256 * 4);   // 782

    zero_kernel<<<128, 256>>>(ei);
    scatter_kernel<<<scat_blocks, 256>>>(ei);
    meta_kernel<<<256, 256>>>(bat);

    // Layer 1
    gemm64<<<gemm_blocks, 128>>>(x, W1, p_feat, NN);
    agg_kernel<true><<<agg_blocks, 256>>>(p_feat, b1, p_h1);

    // Layer 2 (output h, no relu)
    gemm64<<<gemm_blocks, 128>>>(p_h1, W2, p_feat, NN);
    agg_kernel<false><<<agg_blocks, 256>>>(p_feat, b2, out_h);

    // Fused pool + classifier
    poolcls_kernel<<<GG, 64>>>(out_h, out_rep, Wc1, bc1, Wc2, bc2, out_log);
}

// round 10
// speedup vs baseline: 1.1387x; 1.1387x over previous
#include <cuda_runtime.h>
#include <cstdint>

// Problem constants (fixed by the dataset)
#define NN 50000
#define EE 800000
#define HH 64
#define GG 128
#define CC 16
#define CAP 64   // per-node bucket capacity (mean deg = 16; P(deg>63) ~ e^-39)
#define GR 128   // gemm rows per block

// ---------------- device scratch (static, no allocations) ----------------
__device__ int   g_deg[NN];                    // in-degree / bucket fill
__device__ float g_dinv[NN];
__device__ int   g_srcs[(size_t)NN * CAP];     // bucketed CSR
__device__ float g_feat[(size_t)NN * HH];      // layer-1: (X@W1)*dinv
__device__ float g_feat2[(size_t)NN * HH];     // layer-2: (h1@W2)*dinv
__device__ int   g_goff[GG + 1];
__device__ int   g_is64;

// ---------------- index dtype handling ----------------
__device__ __forceinline__ int idx_at(const void* p, int is64, long long i) {
    if (is64) return (int)__ldg(((const long long*)p) + i);
    return __ldg(((const int*)p) + i);
}

// Zero counters + detect index dtype (int64 vs int32).
__global__ void zero_kernel(const void* __restrict__ ei) {
    int i = blockIdx.x * blockDim.x + threadIdx.x;
    int stride = gridDim.x * blockDim.x;
    for (; i < NN; i += stride) g_deg[i] = 0;
    if (blockIdx.x == 0 && threadIdx.x == 0) {
        const unsigned long long* p = (const unsigned long long*)ei;
        int ok = 1;
        for (int t = 0; t < 16; t++)
            if (p[t] >= (unsigned long long)NN) ok = 0;
        g_is64 = ok;
    }
}

// Single-pass bucketed CSR build, unrolled x4 for atomic-latency overlap.
__global__ __launch_bounds__(256) void scatter_kernel(const void* __restrict__ ei) {
    const int U = 4;
    int is64 = g_is64;
    int stride = gridDim.x * blockDim.x;
    int base = blockIdx.x * blockDim.x + threadIdx.x;

    int s[U], d[U], p[U];
    bool ok[U];
#pragma unroll
    for (int u = 0; u < U; u++) {
        int e = base + u * stride;
        ok[u] = (e < EE);
        if (ok[u]) {
            s[u] = idx_at(ei, is64, e);
            d[u] = idx_at(ei, is64, (long long)EE + e);
        }
    }
#pragma unroll
    for (int u = 0; u < U; u++)
        if (ok[u]) p[u] = atomicAdd(&g_deg[d[u]], 1);
#pragma unroll
    for (int u = 0; u < U; u++)
        if (ok[u] && p[u] < CAP) g_srcs[(size_t)d[u] * CAP + p[u]] = s[u];
}

// dinv from final degrees + graph offsets from sorted-batch boundaries.
__global__ void meta_kernel(const void* __restrict__ bat) {
    int is64 = g_is64;
    int i = blockIdx.x * blockDim.x + threadIdx.x;
    int stride = gridDim.x * blockDim.x;
    for (int n = i; n < NN; n += stride) {
        g_dinv[n] = rsqrtf((float)(g_deg[n] + 1));
        int b = idx_at(bat, is64, n);
        int bp = (n == 0) ? -1 : idx_at(bat, is64, n - 1);
        for (int g = bp + 1; g <= b; g++) g_goff[g] = n;
        if (n == NN - 1)
            for (int g = b + 1; g <= GG; g++) g_goff[g] = NN;
    }
}

// out[row,:] = (X[row,:] @ W) * dinv[row].
// 128-row tiles, 128 threads, thread tile = 8 rows x 8 cols.  (R8 version)
__global__ __launch_bounds__(128) void gemm64(const float* __restrict__ X,
                                              const float* __restrict__ W,
                                              float* __restrict__ out,
                                              int n) {
    __shared__ float Xs[64][GR + 4];   // [k][row]
    __shared__ float Ws[64][68];
    const int tid = threadIdx.x;
    const int brow = blockIdx.x * GR;

    for (int t = tid; t < 64 * 16; t += 128) {
        int r = t >> 4, c = (t & 15) << 2;
        *(float4*)&Ws[r][c] = *(const float4*)(W + r * 64 + c);
    }
    for (int t = tid; t < GR * 16; t += 128) {
        int r = t >> 4, c = (t & 15) << 2;
        int grow = brow + r;
        float4 v = make_float4(0.f, 0.f, 0.f, 0.f);
        if (grow < n) v = *(const float4*)(X + (size_t)grow * 64 + c);
        Xs[c][r] = v.x; Xs[c + 1][r] = v.y; Xs[c + 2][r] = v.z; Xs[c + 3][r] = v.w;
    }
    __syncthreads();

    const int r0 = (tid >> 3) << 3;
    const int j0 = (tid & 7) << 3;
    float acc[8][8];
#pragma unroll
    for (int i = 0; i < 8; i++)
#pragma unroll
        for (int j = 0; j < 8; j++) acc[i][j] = 0.f;

#pragma unroll
    for (int k = 0; k < 64; k++) {
        float4 xa = *(const float4*)&Xs[k][r0];
        float4 xb = *(const float4*)&Xs[k][r0 + 4];
        float4 wa = *(const float4*)&Ws[k][j0];
        float4 wb = *(const float4*)&Ws[k][j0 + 4];
        float xr[8] = {xa.x, xa.y, xa.z, xa.w, xb.x, xb.y, xb.z, xb.w};
        float wr[8] = {wa.x, wa.y, wa.z, wa.w, wb.x, wb.y, wb.z, wb.w};
#pragma unroll
        for (int i = 0; i < 8; i++)
#pragma unroll
            for (int j = 0; j < 8; j++)
                acc[i][j] = fmaf(xr[i], wr[j], acc[i][j]);
    }

#pragma unroll
    for (int i = 0; i < 8; i++) {
        int row = brow + r0 + i;
        if (row < n) {
            float dv = g_dinv[row];
            float4 o0 = make_float4(acc[i][0] * dv, acc[i][1] * dv,
                                    acc[i][2] * dv, acc[i][3] * dv);
            float4 o1 = make_float4(acc[i][4] * dv, acc[i][5] * dv,
                                    acc[i][6] * dv, acc[i][7] * dv);
            *(float4*)(out + (size_t)row * 64 + j0) = o0;
            *(float4*)(out + (size_t)row * 64 + j0 + 4) = o1;
        }
    }
}

// Fused layer-1 aggregation + layer-2 transform.
// Per node (1 warp): h1 = relu(dinv*(sum neigh feat + self) + b1), then
// feat2[node,:] = dinv[node] * (h1 @ W2).   h1 staged in smem per warp.
__global__ __launch_bounds__(256) void agg_fuse_kernel(
        const float* __restrict__ gb,      // feat1
        const float* __restrict__ bias1,
        const float* __restrict__ W2,
        float* __restrict__ feat2) {
    __shared__ float Ws2[64][66];       // W2 [k][col], pad 2
    __shared__ float h1buf[8][64];      // per-warp h1 row
    const int tid = threadIdx.x;

    // cooperative W2 load
    for (int t = tid; t < 64 * 16; t += 256) {
        int r = t >> 4, c = (t & 15) << 2;
        float4 w = *(const float4*)(W2 + r * 64 + c);
        Ws2[r][c] = w.x; Ws2[r][c + 1] = w.y; Ws2[r][c + 2] = w.z; Ws2[r][c + 3] = w.w;
    }
    __syncthreads();

    int w = tid >> 5;
    int node = blockIdx.x * 8 + w;
    if (node >= NN) return;
    int lane = tid & 31;
    int sub = lane >> 4;
    int fc = (lane & 15) << 2;
    int beg = node * CAP;
    int end = beg + min(g_deg[node], CAP);

    float4 accA, accB = make_float4(0.f, 0.f, 0.f, 0.f);
    if (sub == 0) {
        accA = *(const float4*)(gb + (size_t)node * 64 + fc);
    } else {
        accA = make_float4(0.f, 0.f, 0.f, 0.f);
    }

    int e = beg + sub;
    for (; e + 2 < end; e += 4) {
        int s0 = __ldg(&g_srcs[e]);
        int s1 = __ldg(&g_srcs[e + 2]);
        float4 v0 = __ldg((const float4*)(gb + (size_t)s0 * 64 + fc));
        float4 v1 = __ldg((const float4*)(gb + (size_t)s1 * 64 + fc));
        accA.x += v0.x; accA.y += v0.y; accA.z += v0.z; accA.w += v0.w;
        accB.x += v1.x; accB.y += v1.y; accB.z += v1.z; accB.w += v1.w;
    }
    if (e < end) {
        int s0 = __ldg(&g_srcs[e]);
        float4 v0 = __ldg((const float4*)(gb + (size_t)s0 * 64 + fc));
        accA.x += v0.x; accA.y += v0.y; accA.z += v0.z; accA.w += v0.w;
    }
    accA.x += accB.x; accA.y += accB.y; accA.z += accB.z; accA.w += accB.w;

    accA.x += __shfl_xor_sync(0xffffffffu, accA.x, 16);
    accA.y += __shfl_xor_sync(0xffffffffu, accA.y, 16);
    accA.z += __shfl_xor_sync(0xffffffffu, accA.z, 16);
    accA.w += __shfl_xor_sync(0xffffffffu, accA.w, 16);

    float dv = g_dinv[node];
    if (sub == 0) {
        float4 b = __ldg((const float4*)(bias1 + fc));
        float4 o;
        o.x = fmaxf(fmaf(accA.x, dv, b.x), 0.f);
        o.y = fmaxf(fmaf(accA.y, dv, b.y), 0.f);
        o.z = fmaxf(fmaf(accA.z, dv, b.z), 0.f);
        o.w = fmaxf(fmaf(accA.w, dv, b.w), 0.f);
        *(float4*)&h1buf[w][fc] = o;
    }
    __syncwarp();

    // matvec: lane computes feat2 cols (2*lane, 2*lane+1)
    float a0 = 0.f, a1 = 0.f;
#pragma unroll
    for (int k4 = 0; k4 < 64; k4 += 4) {
        float4 hk = *(const float4*)&h1buf[w][k4];
        float2 w0 = *(const float2*)&Ws2[k4][2 * lane];
        float2 w1 = *(const float2*)&Ws2[k4 + 1][2 * lane];
        float2 w2v = *(const float2*)&Ws2[k4 + 2][2 * lane];
        float2 w3 = *(const float2*)&Ws2[k4 + 3][2 * lane];
        a0 = fmaf(hk.x, w0.x, a0); a1 = fmaf(hk.x, w0.y, a1);
        a0 = fmaf(hk.y, w1.x, a0); a1 = fmaf(hk.y, w1.y, a1);
        a0 = fmaf(hk.z, w2v.x, a0); a1 = fmaf(hk.z, w2v.y, a1);
        a0 = fmaf(hk.w, w3.x, a0); a1 = fmaf(hk.w, w3.y, a1);
    }
    *(float2*)(feat2 + (size_t)node * 64 + 2 * lane) = make_float2(a0 * dv, a1 * dv);
}

// Layer-2 aggregation: out[d,:] = dinv*(sum feat2[neigh] + self) + b2.
__global__ __launch_bounds__(256) void agg_kernel(const float* __restrict__ gb,
                                                  const float* __restrict__ bias,
                                                  float* __restrict__ out) {
    int warp = (blockIdx.x * blockDim.x + threadIdx.x) >> 5;
    if (warp >= NN) return;
    int lane = threadIdx.x & 31;
    int sub = lane >> 4;
    int fc = (lane & 15) << 2;
    int beg = warp * CAP;
    int end = beg + min(g_deg[warp], CAP);

    float4 accA, accB = make_float4(0.f, 0.f, 0.f, 0.f);
    if (sub == 0) {
        accA = *(const float4*)(gb + (size_t)warp * 64 + fc);
    } else {
        accA = make_float4(0.f, 0.f, 0.f, 0.f);
    }

    int e = beg + sub;
    for (; e + 2 < end; e += 4) {
        int s0 = __ldg(&g_srcs[e]);
        int s1 = __ldg(&g_srcs[e + 2]);
        float4 v0 = __ldg((const float4*)(gb + (size_t)s0 * 64 + fc));
        float4 v1 = __ldg((const float4*)(gb + (size_t)s1 * 64 + fc));
        accA.x += v0.x; accA.y += v0.y; accA.z += v0.z; accA.w += v0.w;
        accB.x += v1.x; accB.y += v1.y; accB.z += v1.z; accB.w += v1.w;
    }
    if (e < end) {
        int s0 = __ldg(&g_srcs[e]);
        float4 v0 = __ldg((const float4*)(gb + (size_t)s0 * 64 + fc));
        accA.x += v0.x; accA.y += v0.y; accA.z += v0.z; accA.w += v0.w;
    }
    accA.x += accB.x; accA.y += accB.y; accA.z += accB.z; accA.w += accB.w;

    accA.x += __shfl_xor_sync(0xffffffffu, accA.x, 16);
    accA.y += __shfl_xor_sync(0xffffffffu, accA.y, 16);
    accA.z += __shfl_xor_sync(0xffffffffu, accA.z, 16);
    accA.w += __shfl_xor_sync(0xffffffffu, accA.w, 16);

    if (sub == 0) {
        float dv = g_dinv[warp];
        float4 b = __ldg((const float4*)(bias + fc));
        float4 o;
        o.x = fmaf(accA.x, dv, b.x);
        o.y = fmaf(accA.y, dv, b.y);
        o.z = fmaf(accA.z, dv, b.z);
        o.w = fmaf(accA.w, dv, b.w);
        *(float4*)(out + (size_t)warp * 64 + fc) = o;
    }
}

// Fused mean pool + classifier: one block per graph, 64 threads.
__global__ __launch_bounds__(64) void poolcls_kernel(
        const float* __restrict__ h, float* __restrict__ reps,
        const float* __restrict__ Wc1, const float* __restrict__ bc1,
        const float* __restrict__ Wc2, const float* __restrict__ bc2,
        float* __restrict__ logits) {
    __shared__ float rep[64];
    __shared__ float tbuf[64];
    int g = blockIdx.x, tid = threadIdx.x;
    int beg = g_goff[g], end = g_goff[g + 1];
    float s = 0.f;
    for (int i = beg; i < end; i++) s += __ldg(h + (size_t)i * 64 + tid);
    float c = (float)max(end - beg, 1);
    float r = s / c;
    reps[g * 64 + tid] = r;
    rep[tid] = r;
    __syncthreads();
    float acc = bc1[tid];
#pragma unroll
    for (int k = 0; k < 64; k++) acc = fmaf(rep[k], __ldg(Wc1 + k * 64 + tid), acc);
    tbuf[tid] = fmaxf(acc, 0.f);
    __syncthreads();
    if (tid < CC) {
        float a = bc2[tid];
#pragma unroll
        for (int k = 0; k < 64; k++) a = fmaf(tbuf[k], __ldg(Wc2 + k * CC + tid), a);
        logits[g * CC + tid] = a;
    }
}

extern "C" void kernel_launch(void* const* d_in, const int* in_sizes, int n_in,
                              void* d_out, int out_size) {
    const float* x   = (const float*)d_in[0];
    const void*  ei  = d_in[1];
    const void*  bat = d_in[2];
    const float* W1  = (const float*)d_in[3];
    const float* b1  = (const float*)d_in[4];
    const float* W2  = (const float*)d_in[5];
    const float* b2  = (const float*)d_in[6];
    const float* Wc1 = (const float*)d_in[7];
    const float* bc1 = (const float*)d_in[8];
    const float* Wc2 = (const float*)d_in[9];
    const float* bc2 = (const float*)d_in[10];

    float* out_h   = (float*)d_out;                       // [NN, 64]
    float* out_rep = out_h + (size_t)NN * HH;             // [128, 64]
    float* out_log = out_rep + (size_t)GG * HH;           // [128, 16]

    void* pv;
    cudaGetSymbolAddress(&pv, g_feat);
    float* p_feat = (float*)pv;
    cudaGetSymbolAddress(&pv, g_feat2);
    float* p_feat2 = (float*)pv;

    const int gemm_blocks = (NN + GR - 1) / GR;
    const int agg_blocks = (NN * 32 + 255) / 256;
    const int fuse_blocks = (NN + 7) / 8;
    const int scat_blocks = (EE + 256 * 4 - 1) / (256 * 4);

    zero_kernel<<<128, 256>>>(ei);
    scatter_kernel<<<scat_blocks, 256>>>(ei);
    meta_kernel<<<256, 256>>>(bat);

    // Layer 1 transform
    gemm64<<<gemm_blocks, 128>>>(x, W1, p_feat, NN);
    // Layer-1 aggregate + layer-2 transform fused
    agg_fuse_kernel<<<fuse_blocks, 256>>>(p_feat, b1, W2, p_feat2);
    // Layer-2 aggregate (writes h output)
    agg_kernel<<<agg_blocks, 256>>>(p_feat2, b2, out_h);

    // Fused pool + classifier
    poolcls_kernel<<<GG, 64>>>(out_h, out_rep, Wc1, bc1, Wc2, bc2, out_log);
}

// round 12
// speedup vs baseline: 1.5610x; 1.3708x over previous
#include <cuda_runtime.h>
#include <cstdint>

// Problem constants (fixed by the dataset)
#define NN 50000
#define EE 800000
#define HH 64
#define GG 128
#define CC 16
#define CAP 64   // per-node bucket capacity (mean deg = 16; P(deg>63) ~ e^-39)

// ---------------- device scratch (static, no allocations) ----------------
__device__ int   g_deg[NN];                    // in-degree / bucket fill
__device__ float g_dinv[NN];
__device__ int   g_srcs[(size_t)NN * CAP];     // bucketed CSR
__device__ float g_feat[(size_t)NN * HH];      // (X@W)*dinv working buffer
__device__ float g_h1[(size_t)NN * HH];        // layer-1 output (post relu)
__device__ int   g_goff[GG + 1];
__device__ int   g_is64;

// ---------------- index dtype handling ----------------
__device__ __forceinline__ int idx_at(const void* p, int is64, long long i) {
    if (is64) return (int)__ldg(((const long long*)p) + i);
    return __ldg(((const int*)p) + i);
}

__device__ __forceinline__ unsigned f2tf(float f) {
    unsigned u;
    asm("cvt.rna.tf32.f32 %0, %1;" : "=r"(u) : "f"(f));
    return u;
}

// Zero counters + detect index dtype (int64 vs int32).
__global__ void zero_kernel(const void* __restrict__ ei) {
    int i = blockIdx.x * blockDim.x + threadIdx.x;
    int stride = gridDim.x * blockDim.x;
    for (; i < NN; i += stride) g_deg[i] = 0;
    if (blockIdx.x == 0 && threadIdx.x == 0) {
        const unsigned long long* p = (const unsigned long long*)ei;
        int ok = 1;
        for (int t = 0; t < 16; t++)
            if (p[t] >= (unsigned long long)NN) ok = 0;
        g_is64 = ok;
    }
}

// Single-pass bucketed CSR build, unrolled x4 for atomic-latency overlap.
__global__ __launch_bounds__(256) void scatter_kernel(const void* __restrict__ ei) {
    const int U = 4;
    int is64 = g_is64;
    int stride = gridDim.x * blockDim.x;
    int base = blockIdx.x * blockDim.x + threadIdx.x;

    int s[U], d[U], p[U];
    bool ok[U];
#pragma unroll
    for (int u = 0; u < U; u++) {
        int e = base + u * stride;
        ok[u] = (e < EE);
        if (ok[u]) {
            s[u] = idx_at(ei, is64, e);
            d[u] = idx_at(ei, is64, (long long)EE + e);
        }
    }
#pragma unroll
    for (int u = 0; u < U; u++)
        if (ok[u]) p[u] = atomicAdd(&g_deg[d[u]], 1);
#pragma unroll
    for (int u = 0; u < U; u++)
        if (ok[u] && p[u] < CAP) g_srcs[(size_t)d[u] * CAP + p[u]] = s[u];
}

// dinv from final degrees + graph offsets from sorted-batch boundaries.
__global__ void meta_kernel(const void* __restrict__ bat) {
    int is64 = g_is64;
    int i = blockIdx.x * blockDim.x + threadIdx.x;
    int stride = gridDim.x * blockDim.x;
    for (int n = i; n < NN; n += stride) {
        g_dinv[n] = rsqrtf((float)(g_deg[n] + 1));
        int b = idx_at(bat, is64, n);
        int bp = (n == 0) ? -1 : idx_at(bat, is64, n - 1);
        for (int g = bp + 1; g <= b; g++) g_goff[g] = n;
        if (n == NN - 1)
            for (int g = b + 1; g <= GG; g++) g_goff[g] = NN;
    }
}

// Tensor-core GEMM: out[row,:] = (X[row,:] @ W) * dinv[row].
// m16n8k8 tf32 mma. 64-row blocks, 128 threads = 4 warps x 16 rows.
// PTX tf32 fragment layout:
//   A: a0=(g,t) a1=(g+8,t) a2=(g,t+4) a3=(g+8,t+4)
//   B: b0=(k=t,n=g) b1=(k=t+4,n=g)
//   C: c0=(g,2t) c1=(g,2t+1) c2=(g+8,2t) c3=(g+8,2t+1)
__global__ __launch_bounds__(128) void gemm_tc(const float* __restrict__ X,
                                               const float* __restrict__ W,
                                               float* __restrict__ out,
                                               int n) {
    __shared__ float    Xs[64][68];     // X tile, row-major
    __shared__ unsigned Wt[64][68];     // W converted to tf32, [k][n]
    const int tid = threadIdx.x;
    const int brow = blockIdx.x * 64;

    // stage W (tf32-converted) and X tile, coalesced
    for (int t = tid; t < 64 * 16; t += 128) {
        int r = t >> 4, c = (t & 15) << 2;
        float4 w = *(const float4*)(W + r * 64 + c);
        Wt[r][c] = f2tf(w.x); Wt[r][c + 1] = f2tf(w.y);
        Wt[r][c + 2] = f2tf(w.z); Wt[r][c + 3] = f2tf(w.w);
        int grow = brow + r;
        float4 v = make_float4(0.f, 0.f, 0.f, 0.f);
        if (grow < n) v = *(const float4*)(X + (size_t)grow * 64 + c);
        *(float4*)&Xs[r][c] = v;
    }
    __syncthreads();

    const int wid = tid >> 5, lane = tid & 31;
    const int g = lane >> 2, t4 = lane & 3;
    const int wr = wid * 16;

    float acc[8][4];
#pragma unroll
    for (int nt = 0; nt < 8; nt++)
#pragma unroll
        for (int j = 0; j < 4; j++) acc[nt][j] = 0.f;

#pragma unroll
    for (int kt = 0; kt < 8; kt++) {
        int k0 = kt * 8;
        // A fragment per PTX tf32 layout
        unsigned a0 = f2tf(Xs[wr + g][k0 + t4]);
        unsigned a1 = f2tf(Xs[wr + g + 8][k0 + t4]);
        unsigned a2 = f2tf(Xs[wr + g][k0 + t4 + 4]);
        unsigned a3 = f2tf(Xs[wr + g + 8][k0 + t4 + 4]);
#pragma unroll
        for (int nt = 0; nt < 8; nt++) {
            unsigned b0 = Wt[k0 + t4][nt * 8 + g];
            unsigned b1 = Wt[k0 + t4 + 4][nt * 8 + g];
            asm("mma.sync.aligned.m16n8k8.row.col.f32.tf32.tf32.f32 "
                "{%0,%1,%2,%3}, {%4,%5,%6,%7}, {%8,%9}, {%0,%1,%2,%3};"
                : "+f"(acc[nt][0]), "+f"(acc[nt][1]),
                  "+f"(acc[nt][2]), "+f"(acc[nt][3])
                : "r"(a0), "r"(a1), "r"(a2), "r"(a3), "r"(b0), "r"(b1));
        }
    }

    int row0 = brow + wr + g;
    int row1 = row0 + 8;
    if (row0 < n) {
        float dv = g_dinv[row0];
#pragma unroll
        for (int nt = 0; nt < 8; nt++)
            *(float2*)(out + (size_t)row0 * 64 + nt * 8 + 2 * t4) =
                make_float2(acc[nt][0] * dv, acc[nt][1] * dv);
    }
    if (row1 < n) {
        float dv = g_dinv[row1];
#pragma unroll
        for (int nt = 0; nt < 8; nt++)
            *(float2*)(out + (size_t)row1 * 64 + nt * 8 + 2 * t4) =
                make_float2(acc[nt][2] * dv, acc[nt][3] * dv);
    }
}

// Pull-style aggregation: one warp per node, 2 edges per step (half-warps),
// inner loop unrolled x2 -> 4 independent gathers in flight per warp.
template <bool RELU>
__global__ __launch_bounds__(256) void agg_kernel(const float* __restrict__ gb,
                                                  const float* __restrict__ bias,
                                                  float* __restrict__ out) {
    int warp = (blockIdx.x * blockDim.x + threadIdx.x) >> 5;
    if (warp >= NN) return;
    int lane = threadIdx.x & 31;
    int sub = lane >> 4;          // which of 2 edges per step
    int fc = (lane & 15) << 2;    // feature offset (float4)
    int beg = warp * CAP;
    int end = beg + min(g_deg[warp], CAP);

    float4 accA, accB = make_float4(0.f, 0.f, 0.f, 0.f);
    if (sub == 0) {               // self-loop term loaded once by half-warp 0
        accA = *(const float4*)(gb + (size_t)warp * 64 + fc);
    } else {
        accA = make_float4(0.f, 0.f, 0.f, 0.f);
    }

    int e = beg + sub;
    for (; e + 2 < end; e += 4) {
        int s0 = __ldg(&g_srcs[e]);
        int s1 = __ldg(&g_srcs[e + 2]);
        float4 v0 = __ldg((const float4*)(gb + (size_t)s0 * 64 + fc));
        float4 v1 = __ldg((const float4*)(gb + (size_t)s1 * 64 + fc));
        accA.x += v0.x; accA.y += v0.y; accA.z += v0.z; accA.w += v0.w;
        accB.x += v1.x; accB.y += v1.y; accB.z += v1.z; accB.w += v1.w;
    }
    if (e < end) {
        int s0 = __ldg(&g_srcs[e]);
        float4 v0 = __ldg((const float4*)(gb + (size_t)s0 * 64 + fc));
        accA.x += v0.x; accA.y += v0.y; accA.z += v0.z; accA.w += v0.w;
    }
    accA.x += accB.x; accA.y += accB.y; accA.z += accB.z; accA.w += accB.w;

    // combine the two half-warps
    accA.x += __shfl_xor_sync(0xffffffffu, accA.x, 16);
    accA.y += __shfl_xor_sync(0xffffffffu, accA.y, 16);
    accA.z += __shfl_xor_sync(0xffffffffu, accA.z, 16);
    accA.w += __shfl_xor_sync(0xffffffffu, accA.w, 16);

    if (sub == 0) {
        float dv = g_dinv[warp];
        float4 b = __ldg((const float4*)(bias + fc));
        float4 o;
        o.x = fmaf(accA.x, dv, b.x);
        o.y = fmaf(accA.y, dv, b.y);
        o.z = fmaf(accA.z, dv, b.z);
        o.w = fmaf(accA.w, dv, b.w);
        if (RELU) {
            o.x = fmaxf(o.x, 0.f); o.y = fmaxf(o.y, 0.f);
            o.z = fmaxf(o.z, 0.f); o.w = fmaxf(o.w, 0.f);
        }
        *(float4*)(out + (size_t)warp * 64 + fc) = o;
    }
}

// Fused mean pool + classifier: one block per graph, 64 threads.
__global__ __launch_bounds__(64) void poolcls_kernel(
        const float* __restrict__ h, float* __restrict__ reps,
        const float* __restrict__ Wc1, const float* __restrict__ bc1,
        const float* __restrict__ Wc2, const float* __restrict__ bc2,
        float* __restrict__ logits) {
    __shared__ float rep[64];
    __shared__ float tbuf[64];
    int g = blockIdx.x, tid = threadIdx.x;
    int beg = g_goff[g], end = g_goff[g + 1];
    float s = 0.f;
    for (int i = beg; i < end; i++) s += __ldg(h + (size_t)i * 64 + tid);
    float c = (float)max(end - beg, 1);
    float r = s / c;
    reps[g * 64 + tid] = r;
    rep[tid] = r;
    __syncthreads();
    float acc = bc1[tid];
#pragma unroll
    for (int k = 0; k < 64; k++) acc = fmaf(rep[k], __ldg(Wc1 + k * 64 + tid), acc);
    tbuf[tid] = fmaxf(acc, 0.f);
    __syncthreads();
    if (tid < CC) {
        float a = bc2[tid];
#pragma unroll
        for (int k = 0; k < 64; k++) a = fmaf(tbuf[k], __ldg(Wc2 + k * CC + tid), a);
        logits[g * CC + tid] = a;
    }
}

extern "C" void kernel_launch(void* const* d_in, const int* in_sizes, int n_in,
                              void* d_out, int out_size) {
    const float* x   = (const float*)d_in[0];
    const void*  ei  = d_in[1];
    const void*  bat = d_in[2];
    const float* W1  = (const float*)d_in[3];
    const float* b1  = (const float*)d_in[4];
    const float* W2  = (const float*)d_in[5];
    const float* b2  = (const float*)d_in[6];
    const float* Wc1 = (const float*)d_in[7];
    const float* bc1 = (const float*)d_in[8];
    const float* Wc2 = (const float*)d_in[9];
    const float* bc2 = (const float*)d_in[10];

    float* out_h   = (float*)d_out;                       // [NN, 64]
    float* out_rep = out_h + (size_t)NN * HH;             // [128, 64]
    float* out_log = out_rep + (size_t)GG * HH;           // [128, 16]

    void* pv;
    cudaGetSymbolAddress(&pv, g_feat);
    float* p_feat = (float*)pv;
    cudaGetSymbolAddress(&pv, g_h1);
    float* p_h1 = (float*)pv;

    const int gemm_blocks = (NN + 63) / 64;               // 782
    const int agg_blocks = (NN * 32 + 255) / 256;
    const int scat_blocks = (EE + 256 * 4 - 1) / (256 * 4);

    zero_kernel<<<128, 256>>>(ei);
    scatter_kernel<<<scat_blocks, 256>>>(ei);
    meta_kernel<<<256, 256>>>(bat);

    // Layer 1
    gemm_tc<<<gemm_blocks, 128>>>(x, W1, p_feat, NN);
    agg_kernel<true><<<agg_blocks, 256>>>(p_feat, b1, p_h1);

    // Layer 2 (output h, no relu)
    gemm_tc<<<gemm_blocks, 128>>>(p_h1, W2, p_feat, NN);
    agg_kernel<false><<<agg_blocks, 256>>>(p_feat, b2, out_h);

    // Fused pool + classifier
    poolcls_kernel<<<GG, 64>>>(out_h, out_rep, Wc1, bc1, Wc2, bc2, out_log);
}